// round 3
// baseline (speedup 1.0000x reference)
#include <cuda_runtime.h>
#include <cuda_bf16.h>
#include <cstdint>
#include <cstddef>

// Problem constants
#define BB 128
#define TT 512
#define II 256
#define HH 512
#define G3 1536   // 3*H

// ---------------------------------------------------------------------------
// Device scratch (allocation-free rule: __device__ globals)
// ---------------------------------------------------------------------------
// x_gates[t][b][g]  (t-major so the recurrence reads a contiguous-ish slab per step)
__device__ float g_xg[(size_t)TT * BB * G3];     // ~402 MB
// double-buffered hidden state h[buf][b][j]
__device__ float g_h[2][BB * HH];
// grid barrier state
__device__ unsigned g_cnt;
__device__ unsigned g_gen;

// ---------------------------------------------------------------------------
// Kernel A: x_gates = X @ W_ih^T + b_ih
//   X:   [B*T, 256] row-major (encoder_inputs [B,T,I] flattened; row m = b*T+t)
//   Wih: [1536, 256]
//   out: g_xg[t][b][g]
// Tiled fp32 GEMM: CTA 64x64, 256 threads, thread tile 4x4, Kc=32.
// ---------------------------------------------------------------------------
#define KA_M 64
#define KA_N 64
#define KA_K 32
#define KA_PAD 4

__global__ void __launch_bounds__(256) xproj_kernel(
    const float* __restrict__ X,
    const float* __restrict__ Wih,
    const float* __restrict__ bih)
{
    __shared__ float sA[KA_K][KA_M + KA_PAD];  // [k][m]
    __shared__ float sB[KA_K][KA_N + KA_PAD];  // [k][n]

    const int m0 = blockIdx.y * KA_M;
    const int n0 = blockIdx.x * KA_N;
    const int tid = threadIdx.x;
    const int tx = tid & 15;        // 0..15 -> n
    const int ty = tid >> 4;        // 0..15 -> m

    float acc[4][4];
#pragma unroll
    for (int i = 0; i < 4; i++)
#pragma unroll
        for (int j = 0; j < 4; j++) acc[i][j] = 0.f;

    for (int kt = 0; kt < II; kt += KA_K) {
        // stage A tile (coalesced on k)
#pragma unroll
        for (int i = tid; i < KA_M * KA_K; i += 256) {
            int m = i >> 5, k = i & 31;
            sA[k][m] = X[(size_t)(m0 + m) * II + kt + k];
        }
        // stage B tile
#pragma unroll
        for (int i = tid; i < KA_N * KA_K; i += 256) {
            int n = i >> 5, k = i & 31;
            sB[k][n] = Wih[(size_t)(n0 + n) * II + kt + k];
        }
        __syncthreads();

#pragma unroll
        for (int k = 0; k < KA_K; k++) {
            float4 a = *(const float4*)&sA[k][ty * 4];
            float4 b = *(const float4*)&sB[k][tx * 4];
            acc[0][0] = fmaf(a.x, b.x, acc[0][0]);
            acc[0][1] = fmaf(a.x, b.y, acc[0][1]);
            acc[0][2] = fmaf(a.x, b.z, acc[0][2]);
            acc[0][3] = fmaf(a.x, b.w, acc[0][3]);
            acc[1][0] = fmaf(a.y, b.x, acc[1][0]);
            acc[1][1] = fmaf(a.y, b.y, acc[1][1]);
            acc[1][2] = fmaf(a.y, b.z, acc[1][2]);
            acc[1][3] = fmaf(a.y, b.w, acc[1][3]);
            acc[2][0] = fmaf(a.z, b.x, acc[2][0]);
            acc[2][1] = fmaf(a.z, b.y, acc[2][1]);
            acc[2][2] = fmaf(a.z, b.z, acc[2][2]);
            acc[2][3] = fmaf(a.z, b.w, acc[2][3]);
            acc[3][0] = fmaf(a.w, b.x, acc[3][0]);
            acc[3][1] = fmaf(a.w, b.y, acc[3][1]);
            acc[3][2] = fmaf(a.w, b.z, acc[3][2]);
            acc[3][3] = fmaf(a.w, b.w, acc[3][3]);
        }
        __syncthreads();
    }

    // epilogue: add bias, scatter into [t][b][g]
    float bi[4];
#pragma unroll
    for (int jn = 0; jn < 4; jn++) bi[jn] = bih[n0 + tx * 4 + jn];

#pragma unroll
    for (int im = 0; im < 4; im++) {
        int m = m0 + ty * 4 + im;
        int b = m >> 9;       // /T
        int t = m & 511;      // %T
        float* dst = g_xg + ((size_t)t * BB + b) * G3 + n0 + tx * 4;
#pragma unroll
        for (int jn = 0; jn < 4; jn++) dst[jn] = acc[im][jn] + bi[jn];
    }
}

// ---------------------------------------------------------------------------
// Kernel B: persistent GRU recurrence.
// Grid = 128 CTAs (4 batch-tiles x 32 j-tiles), 256 threads, 1 CTA/SM resident.
// Each CTA owns W_hh rows {j, 512+j, 1024+j : j in its 16-wide j-tile} (96 KB),
// kept in SMEM for all 512 steps. h double-buffered in global (L2 via ldcg/stcg).
// ---------------------------------------------------------------------------
#define NBT 4
#define NJT 32
#define NCTA (NBT * NJT)     // 128
#define BT 32                // batches per CTA
#define JT 16                // hidden units per CTA
#define WROWS (3 * JT)       // 48 W_hh rows
#define WS 516               // smem row stride (floats): %32 = 4, 16B aligned
#define HS 516
#define SMEM_FLOATS (WROWS * WS + BT * HS)
#define SMEM_BYTES (SMEM_FLOATS * 4)

__device__ __forceinline__ void grid_sync()
{
    __threadfence();          // make this CTA's h-stores visible at L2
    __syncthreads();
    if (threadIdx.x == 0) {
        volatile unsigned* vgen = &g_gen;
        unsigned gen = *vgen;
        if (atomicAdd(&g_cnt, 1u) == NCTA - 1) {
            atomicExch(&g_cnt, 0u);
            __threadfence();
            atomicExch(&g_gen, gen + 1u);
        } else {
            while (*vgen == gen) { __nanosleep(64); }
            __threadfence();  // acquire side
        }
    }
    __syncthreads();
}

__device__ __forceinline__ float sigf(float x)
{
    return 1.0f / (1.0f + expf(-x));
}

__global__ void __launch_bounds__(256, 1) gru_rec_kernel(
    const float* __restrict__ Whh,
    const float* __restrict__ bhh,
    float* __restrict__ out)
{
    extern __shared__ float smem[];
    float* sW = smem;                 // [48][WS]
    float* sH = smem + WROWS * WS;    // [32][HS]

    const int tid = threadIdx.x;
    const int bt  = blockIdx.x / NJT;
    const int jt  = blockIdx.x % NJT;
    const int b0  = bt * BT;
    const int j0  = jt * JT;

    // Load resident W_hh slice: row r -> W_hh[(r/16)*512 + j0 + (r%16)][:]
    for (int i = tid; i < WROWS * HH; i += 256) {
        int r = i >> 9, k = i & 511;
        int grow = (r >> 4) * HH + j0 + (r & 15);
        sW[r * WS + k] = Whh[(size_t)grow * HH + k];
    }

    // Zero h[0] tile (this CTA's (b,j) ownership)
    for (int i = tid; i < BT * JT; i += 256) {
        int bl = i / JT, jj = i % JT;
        __stcg(&g_h[0][(size_t)(b0 + bl) * HH + j0 + jj], 0.0f);
    }

    // Per-thread work assignment: 2 batches x 1 j x 3 gates
    const int jj = tid & 15;
    const int bg = tid >> 4;          // 0..15
    const int bA = 2 * bg;
    const int bB = bA + 1;

    const float bhhR = bhh[j0 + jj];
    const float bhhZ = bhh[HH + j0 + jj];
    const float bhhN = bhh[2 * HH + j0 + jj];

    const float* wr = sW + (0 * JT + jj) * WS;
    const float* wz = sW + (1 * JT + jj) * WS;
    const float* wn = sW + (2 * JT + jj) * WS;
    const float* hA = sH + bA * HS;
    const float* hB = sH + bB * HS;

    grid_sync();   // W slices + zeroed h visible everywhere

    for (int t = 0; t < TT; t++) {
        const int cur = t & 1;
        const float* hsrc = g_h[cur] + (size_t)b0 * HH;

        // Stage h tile [32][512] via L2 (coherent across SMs)
        const float2* src2 = (const float2*)hsrc;
        for (int i = tid; i < BT * (HH / 2); i += 256) {
            int bl = i >> 8, k2 = i & 255;
            float2 v = __ldcg(src2 + (size_t)bl * (HH / 2) + k2);
            *(float2*)(sH + bl * HS + 2 * k2) = v;
        }

        // Prefetch x-gate values for this step (overlaps with staging/sync)
        const float* xga = g_xg + ((size_t)t * BB + (b0 + bA)) * G3 + j0 + jj;
        const float* xgb = g_xg + ((size_t)t * BB + (b0 + bB)) * G3 + j0 + jj;
        float xrA = xga[0], xzA = xga[HH], xnA = xga[2 * HH];
        float xrB = xgb[0], xzB = xgb[HH], xnB = xgb[2 * HH];

        __syncthreads();

        float aR = bhhR, aZ = bhhZ, aN = bhhN;
        float bR = bhhR, bZ = bhhZ, bN = bhhN;

#pragma unroll 8
        for (int k = 0; k < HH; k += 4) {
            float4 ha = *(const float4*)(hA + k);
            float4 hb = *(const float4*)(hB + k);
            float4 r4 = *(const float4*)(wr + k);
            float4 z4 = *(const float4*)(wz + k);
            float4 n4 = *(const float4*)(wn + k);

            aR = fmaf(ha.x, r4.x, aR); aR = fmaf(ha.y, r4.y, aR);
            aR = fmaf(ha.z, r4.z, aR); aR = fmaf(ha.w, r4.w, aR);
            aZ = fmaf(ha.x, z4.x, aZ); aZ = fmaf(ha.y, z4.y, aZ);
            aZ = fmaf(ha.z, z4.z, aZ); aZ = fmaf(ha.w, z4.w, aZ);
            aN = fmaf(ha.x, n4.x, aN); aN = fmaf(ha.y, n4.y, aN);
            aN = fmaf(ha.z, n4.z, aN); aN = fmaf(ha.w, n4.w, aN);

            bR = fmaf(hb.x, r4.x, bR); bR = fmaf(hb.y, r4.y, bR);
            bR = fmaf(hb.z, r4.z, bR); bR = fmaf(hb.w, r4.w, bR);
            bZ = fmaf(hb.x, z4.x, bZ); bZ = fmaf(hb.y, z4.y, bZ);
            bZ = fmaf(hb.z, z4.z, bZ); bZ = fmaf(hb.w, z4.w, bZ);
            bN = fmaf(hb.x, n4.x, bN); bN = fmaf(hb.y, n4.y, bN);
            bN = fmaf(hb.z, n4.z, bN); bN = fmaf(hb.w, n4.w, bN);
        }

        // Gate nonlinearity + state update (PyTorch order: r, z, n)
        float rA = sigf(xrA + aR);
        float zA = sigf(xzA + aZ);
        float nA = tanhf(xnA + rA * aN);
        float holdA = hA[j0 + jj];
        float hnewA = fmaf(zA, holdA - nA, nA);   // (1-z)n + z h

        float rB = sigf(xrB + bR);
        float zB = sigf(xzB + bZ);
        float nB = tanhf(xnB + rB * bN);
        float holdB = hB[j0 + jj];
        float hnewB = fmaf(zB, holdB - nB, nB);

        if (t == TT - 1) {
            out[(size_t)(b0 + bA) * HH + j0 + jj] = hnewA;
            out[(size_t)(b0 + bB) * HH + j0 + jj] = hnewB;
        } else {
            __stcg(&g_h[cur ^ 1][(size_t)(b0 + bA) * HH + j0 + jj], hnewA);
            __stcg(&g_h[cur ^ 1][(size_t)(b0 + bB) * HH + j0 + jj], hnewB);
        }

        grid_sync();
    }
}

// ---------------------------------------------------------------------------
// Launcher
// ---------------------------------------------------------------------------
extern "C" void kernel_launch(void* const* d_in, const int* in_sizes, int n_in,
                              void* d_out, int out_size)
{
    const float* X   = (const float*)d_in[0];  // [128,512,256]
    const float* Wih = (const float*)d_in[1];  // [1536,256]
    const float* Whh = (const float*)d_in[2];  // [1536,512]
    const float* bih = (const float*)d_in[3];  // [1536]
    const float* bhh = (const float*)d_in[4];  // [1536]
    float* out = (float*)d_out;                // [1,128,512]

    (void)in_sizes; (void)n_in; (void)out_size;

    // Kernel A: x-projection GEMM into g_xg
    dim3 gA(G3 / KA_N, (BB * TT) / KA_M);      // (24, 1024)
    xproj_kernel<<<gA, 256>>>(X, Wih, bih);

    // Kernel B: persistent recurrence
    cudaFuncSetAttribute(gru_rec_kernel,
                         cudaFuncAttributeMaxDynamicSharedMemorySize, SMEM_BYTES);
    gru_rec_kernel<<<NCTA, 256, SMEM_BYTES>>>(Whh, bhh, out);
}

// round 4
// speedup vs baseline: 1.0293x; 1.0293x over previous
#include <cuda_runtime.h>
#include <cuda_bf16.h>
#include <cstdint>
#include <cstddef>

// Problem constants
#define BB 128
#define TT 512
#define II 256
#define HH 512
#define G3 1536   // 3*H

typedef unsigned long long u64;

// ---------------------------------------------------------------------------
// f32x2 packed-FMA helpers (sm_100+)
// ---------------------------------------------------------------------------
__device__ __forceinline__ u64 pk2(float lo, float hi)
{
    u64 d;
    asm("mov.b64 %0, {%1, %2};" : "=l"(d)
        : "r"(__float_as_uint(lo)), "r"(__float_as_uint(hi)));
    return d;
}
__device__ __forceinline__ u64 fma2(u64 a, u64 b, u64 c)
{
    u64 d;
    asm("fma.rn.f32x2 %0, %1, %2, %3;" : "=l"(d) : "l"(a), "l"(b), "l"(c));
    return d;
}
__device__ __forceinline__ float rsum2(u64 v)
{
    unsigned a, b;
    asm("mov.b64 {%0, %1}, %2;" : "=r"(a), "=r"(b) : "l"(v));
    return __uint_as_float(a) + __uint_as_float(b);
}

// ---------------------------------------------------------------------------
// Device scratch (allocation-free rule: __device__ globals)
// ---------------------------------------------------------------------------
__device__ float g_xg[(size_t)TT * BB * G3];     // x-projection [t][b][3H], ~402 MB
__device__ float g_h[2][BB * HH];                // double-buffered hidden state

struct Bar { unsigned cnt; unsigned gen; unsigned pad[30]; };
__device__ Bar g_bar[4];                         // one barrier per batch-tile group

// ---------------------------------------------------------------------------
// Kernel A: x_gates = X @ W_ih^T + b_ih   (f32x2 version)
//   X:   [B*T, 256] row-major (row m = b*T + t)
//   Wih: [1536, 256]
//   out: g_xg[t][b][g]
// CTA 64x64, 256 threads, thread tile 4m x 4n (as 4m x 2 n-pairs), Kc=32.
// ---------------------------------------------------------------------------
#define KA_M 64
#define KA_N 64
#define KA_K 32
#define KA_PAD 4

__global__ void __launch_bounds__(256) xproj_kernel(
    const float* __restrict__ X,
    const float* __restrict__ Wih,
    const float* __restrict__ bih)
{
    __shared__ float sA[KA_K][KA_M + KA_PAD];  // [k][m]
    __shared__ float sB[KA_K][KA_N + KA_PAD];  // [k][n]

    const int m0 = blockIdx.y * KA_M;
    const int n0 = blockIdx.x * KA_N;
    const int tid = threadIdx.x;
    const int tx = tid & 15;        // n
    const int ty = tid >> 4;        // m

    u64 acc2[4][2];
#pragma unroll
    for (int i = 0; i < 4; i++) { acc2[i][0] = 0ull; acc2[i][1] = 0ull; }

    for (int kt = 0; kt < II; kt += KA_K) {
#pragma unroll
        for (int i = tid; i < KA_M * KA_K; i += 256) {
            int m = i >> 5, k = i & 31;
            sA[k][m] = X[(size_t)(m0 + m) * II + kt + k];
        }
#pragma unroll
        for (int i = tid; i < KA_N * KA_K; i += 256) {
            int n = i >> 5, k = i & 31;
            sB[k][n] = Wih[(size_t)(n0 + n) * II + kt + k];
        }
        __syncthreads();

#pragma unroll
        for (int k = 0; k < KA_K; k++) {
            float4 a = *(const float4*)&sA[k][ty * 4];
            ulonglong2 b2 = *(const ulonglong2*)&sB[k][tx * 4];  // (n,n+1),(n+2,n+3)
            u64 a0 = pk2(a.x, a.x);
            u64 a1 = pk2(a.y, a.y);
            u64 a2 = pk2(a.z, a.z);
            u64 a3 = pk2(a.w, a.w);
            acc2[0][0] = fma2(a0, b2.x, acc2[0][0]);
            acc2[0][1] = fma2(a0, b2.y, acc2[0][1]);
            acc2[1][0] = fma2(a1, b2.x, acc2[1][0]);
            acc2[1][1] = fma2(a1, b2.y, acc2[1][1]);
            acc2[2][0] = fma2(a2, b2.x, acc2[2][0]);
            acc2[2][1] = fma2(a2, b2.y, acc2[2][1]);
            acc2[3][0] = fma2(a3, b2.x, acc2[3][0]);
            acc2[3][1] = fma2(a3, b2.y, acc2[3][1]);
        }
        __syncthreads();
    }

    // epilogue: add bias, scatter into [t][b][g]
    float bi[4];
#pragma unroll
    for (int jn = 0; jn < 4; jn++) bi[jn] = bih[n0 + tx * 4 + jn];

#pragma unroll
    for (int im = 0; im < 4; im++) {
        int m = m0 + ty * 4 + im;
        int b = m >> 9;       // /T
        int t = m & 511;      // %T
        float* dst = g_xg + ((size_t)t * BB + b) * G3 + n0 + tx * 4;
#pragma unroll
        for (int jp = 0; jp < 2; jp++) {
            unsigned lo, hi;
            asm("mov.b64 {%0, %1}, %2;" : "=r"(lo), "=r"(hi) : "l"(acc2[im][jp]));
            dst[2 * jp]     = __uint_as_float(lo) + bi[2 * jp];
            dst[2 * jp + 1] = __uint_as_float(hi) + bi[2 * jp + 1];
        }
    }
}

// ---------------------------------------------------------------------------
// Kernel B: persistent GRU recurrence, lane=batch layout + f32x2.
// Grid = 128 CTAs (4 batch-tiles x 32 j-tiles), 256 threads, 1 CTA/SM.
// Warp w owns hidden units {j0+2w, j0+2w+1} (6 gate-rows, broadcast LDS);
// lane l owns batch b0+l. W_hh slice (48x512, 96KB) resident in SMEM.
// ---------------------------------------------------------------------------
#define NBT 4
#define NJT 32
#define NCTA (NBT * NJT)     // 128
#define BT 32                // batches per CTA
#define JT 16                // hidden units per CTA
#define WROWS (3 * JT)       // 48 W_hh rows
#define WS 516               // smem row stride (floats): %32 == 4, 16B aligned
#define HS 516
#define SMEM_FLOATS (WROWS * WS + BT * HS)
#define SMEM_BYTES (SMEM_FLOATS * 4)

__device__ __forceinline__ void group_sync(int bt)
{
    __threadfence();          // release: h-stores visible at L2
    __syncthreads();
    if (threadIdx.x == 0) {
        volatile unsigned* vgen = &g_bar[bt].gen;
        unsigned gen = *vgen;
        if (atomicAdd(&g_bar[bt].cnt, 1u) == NJT - 1) {
            atomicExch(&g_bar[bt].cnt, 0u);
            __threadfence();
            atomicExch((unsigned*)&g_bar[bt].gen, gen + 1u);
        } else {
            while (*vgen == gen) { __nanosleep(32); }
            __threadfence();  // acquire
        }
    }
    __syncthreads();
}

__device__ __forceinline__ float sigf(float x)
{
    return 1.0f / (1.0f + expf(-x));
}

__global__ void __launch_bounds__(256, 1) gru_rec_kernel(
    const float* __restrict__ Whh,
    const float* __restrict__ bhh,
    float* __restrict__ out)
{
    extern __shared__ float smem[];
    float* sW = smem;                 // [48][WS]
    float* sH = smem + WROWS * WS;    // [32][HS]

    const int tid  = threadIdx.x;
    const int bt   = blockIdx.x / NJT;
    const int jt   = blockIdx.x % NJT;
    const int b0   = bt * BT;
    const int j0   = jt * JT;
    const int lane = tid & 31;
    const int w    = tid >> 5;        // warp 0..7
    const int jlA  = 2 * w;           // local j (even)
    const int jA   = j0 + jlA;        // global j

    // Load resident W_hh slice: smem row r=(g*16+jl) <- W_hh[g*512 + j0 + jl][:]
    for (int i = tid; i < WROWS * HH; i += 256) {
        int r = i >> 9, k = i & 511;
        int grow = (r >> 4) * HH + j0 + (r & 15);
        sW[r * WS + k] = Whh[(size_t)grow * HH + k];
    }

    // Zero h[0] for this CTA's (b, j) tile: thread (w, lane) owns (b0+lane, jA..jA+1)
    {
        float2 z2 = make_float2(0.f, 0.f);
        *(float2*)&g_h[0][(size_t)(b0 + lane) * HH + jA] = z2;
        __threadfence();
    }

    const float bhR0 = bhh[jA],          bhR1 = bhh[jA + 1];
    const float bhZ0 = bhh[HH + jA],     bhZ1 = bhh[HH + jA + 1];
    const float bhN0 = bhh[2 * HH + jA], bhN1 = bhh[2 * HH + jA + 1];

    const float* wR0 = sW + (0 * JT + jlA) * WS;
    const float* wR1 = sW + (0 * JT + jlA + 1) * WS;
    const float* wZ0 = sW + (1 * JT + jlA) * WS;
    const float* wZ1 = sW + (1 * JT + jlA + 1) * WS;
    const float* wN0 = sW + (2 * JT + jlA) * WS;
    const float* wN1 = sW + (2 * JT + jlA + 1) * WS;
    const float* hrow = sH + lane * HS;

    group_sync(bt);   // zeroed h visible within batch-group

    for (int t = 0; t < TT; t++) {
        const int cur = t & 1;

        // Prefetch this thread's x-gate values (DRAM; overlap with staging)
        const float* xb = g_xg + ((size_t)t * BB + b0 + lane) * G3 + jA;
        float2 xr = *(const float2*)(xb);
        float2 xz = *(const float2*)(xb + HH);
        float2 xn = *(const float2*)(xb + 2 * HH);

        // Stage h tile [32][512] from L2 into smem (coherent via ldcg)
        const float4* src4 = (const float4*)(g_h[cur] + (size_t)b0 * HH);
#pragma unroll
        for (int i = tid; i < BT * (HH / 4); i += 256) {
            int bl = i >> 7, k4 = i & 127;
            float4 v = __ldcg(src4 + (size_t)bl * (HH / 4) + k4);
            *(float4*)(sH + bl * HS + 4 * k4) = v;
        }
        __syncthreads();

        u64 cR0 = pk2(bhR0, 0.f), cR1 = pk2(bhR1, 0.f);
        u64 cZ0 = pk2(bhZ0, 0.f), cZ1 = pk2(bhZ1, 0.f);
        u64 cN0 = pk2(bhN0, 0.f), cN1 = pk2(bhN1, 0.f);

#pragma unroll 4
        for (int k = 0; k < HH; k += 4) {
            ulonglong2 h2 = *(const ulonglong2*)(hrow + k);   // (k,k+1),(k+2,k+3)
            ulonglong2 r0 = *(const ulonglong2*)(wR0 + k);
            ulonglong2 r1 = *(const ulonglong2*)(wR1 + k);
            ulonglong2 z0 = *(const ulonglong2*)(wZ0 + k);
            ulonglong2 z1 = *(const ulonglong2*)(wZ1 + k);
            ulonglong2 n0 = *(const ulonglong2*)(wN0 + k);
            ulonglong2 n1 = *(const ulonglong2*)(wN1 + k);

            cR0 = fma2(h2.x, r0.x, cR0); cR0 = fma2(h2.y, r0.y, cR0);
            cR1 = fma2(h2.x, r1.x, cR1); cR1 = fma2(h2.y, r1.y, cR1);
            cZ0 = fma2(h2.x, z0.x, cZ0); cZ0 = fma2(h2.y, z0.y, cZ0);
            cZ1 = fma2(h2.x, z1.x, cZ1); cZ1 = fma2(h2.y, z1.y, cZ1);
            cN0 = fma2(h2.x, n0.x, cN0); cN0 = fma2(h2.y, n0.y, cN0);
            cN1 = fma2(h2.x, n1.x, cN1); cN1 = fma2(h2.y, n1.y, cN1);
        }

        float aR0 = rsum2(cR0), aR1 = rsum2(cR1);
        float aZ0 = rsum2(cZ0), aZ1 = rsum2(cZ1);
        float aN0 = rsum2(cN0), aN1 = rsum2(cN1);

        float2 hold2 = *(const float2*)(hrow + jA);

        // PyTorch gate order: r, z, n
        float r0v = sigf(xr.x + aR0);
        float z0v = sigf(xz.x + aZ0);
        float n0v = tanhf(xn.x + r0v * aN0);
        float hn0 = fmaf(z0v, hold2.x - n0v, n0v);   // (1-z)n + z h

        float r1v = sigf(xr.y + aR1);
        float z1v = sigf(xz.y + aZ1);
        float n1v = tanhf(xn.y + r1v * aN1);
        float hn1 = fmaf(z1v, hold2.y - n1v, n1v);

        if (t == TT - 1) {
            float2 hw = make_float2(hn0, hn1);
            *(float2*)&out[(size_t)(b0 + lane) * HH + jA] = hw;
        } else {
            float2 hw = make_float2(hn0, hn1);
            __stcg((float2*)&g_h[cur ^ 1][(size_t)(b0 + lane) * HH + jA], hw);
        }

        group_sync(bt);
    }
}

// ---------------------------------------------------------------------------
// Launcher
// ---------------------------------------------------------------------------
extern "C" void kernel_launch(void* const* d_in, const int* in_sizes, int n_in,
                              void* d_out, int out_size)
{
    const float* X   = (const float*)d_in[0];  // [128,512,256]
    const float* Wih = (const float*)d_in[1];  // [1536,256]
    const float* Whh = (const float*)d_in[2];  // [1536,512]
    const float* bih = (const float*)d_in[3];  // [1536]
    const float* bhh = (const float*)d_in[4];  // [1536]
    float* out = (float*)d_out;                // [1,128,512]

    (void)in_sizes; (void)n_in; (void)out_size;

    dim3 gA(G3 / KA_N, (BB * TT) / KA_M);      // (24, 1024)
    xproj_kernel<<<gA, 256>>>(X, Wih, bih);

    cudaFuncSetAttribute(gru_rec_kernel,
                         cudaFuncAttributeMaxDynamicSharedMemorySize, SMEM_BYTES);
    gru_rec_kernel<<<NCTA, 256, SMEM_BYTES>>>(Whh, bhh, out);
}

// round 7
// speedup vs baseline: 1.1016x; 1.0702x over previous
#include <cuda_runtime.h>
#include <cuda_bf16.h>
#include <cstdint>
#include <cstddef>

// Problem constants
#define BB 128
#define TT 512
#define II 256
#define HH 512
#define G3 1536   // 3*H

typedef unsigned long long u64;

// ---------------------------------------------------------------------------
// f32x2 packed helpers (sm_100+)
// ---------------------------------------------------------------------------
__device__ __forceinline__ u64 pk2(float lo, float hi)
{
    u64 d;
    asm("mov.b64 %0, {%1, %2};" : "=l"(d)
        : "r"(__float_as_uint(lo)), "r"(__float_as_uint(hi)));
    return d;
}
__device__ __forceinline__ u64 fma2(u64 a, u64 b, u64 c)
{
    u64 d;
    asm("fma.rn.f32x2 %0, %1, %2, %3;" : "=l"(d) : "l"(a), "l"(b), "l"(c));
    return d;
}
__device__ __forceinline__ u64 add2(u64 a, u64 b)
{
    u64 d;
    asm("add.rn.f32x2 %0, %1, %2;" : "=l"(d) : "l"(a), "l"(b));
    return d;
}
__device__ __forceinline__ float rsum2(u64 v)
{
    unsigned a, b;
    asm("mov.b64 {%0, %1}, %2;" : "=r"(a), "=r"(b) : "l"(v));
    return __uint_as_float(a) + __uint_as_float(b);
}
__device__ __forceinline__ float2 unpk2(u64 v)
{
    unsigned a, b;
    asm("mov.b64 {%0, %1}, %2;" : "=r"(a), "=r"(b) : "l"(v));
    return make_float2(__uint_as_float(a), __uint_as_float(b));
}
__device__ __forceinline__ u64 shfl_xor_u64(u64 v, int m)
{
    unsigned lo, hi;
    asm("mov.b64 {%0, %1}, %2;" : "=r"(lo), "=r"(hi) : "l"(v));
    lo = __shfl_xor_sync(0xffffffffu, lo, m);
    hi = __shfl_xor_sync(0xffffffffu, hi, m);
    u64 d;
    asm("mov.b64 %0, {%1, %2};" : "=l"(d) : "r"(lo), "r"(hi));
    return d;
}

// ---------------------------------------------------------------------------
// Device scratch (allocation-free rule: __device__ globals)
// ---------------------------------------------------------------------------
__device__ float g_xg[(size_t)TT * BB * G3];     // x-projection [t][b][3H], ~402 MB
__device__ float g_h[2][BB * HH];                // double-buffered hidden state

struct Bar { unsigned cnt; unsigned gen; unsigned pad[30]; };
__device__ Bar g_bar[4];                         // one barrier per batch-tile group

// ---------------------------------------------------------------------------
// Kernel A: x_gates = X @ W_ih^T + b_ih   (f32x2 version)
// ---------------------------------------------------------------------------
#define KA_M 64
#define KA_N 64
#define KA_K 32
#define KA_PAD 4

__global__ void __launch_bounds__(256) xproj_kernel(
    const float* __restrict__ X,
    const float* __restrict__ Wih,
    const float* __restrict__ bih)
{
    __shared__ float sA[KA_K][KA_M + KA_PAD];  // [k][m]
    __shared__ float sB[KA_K][KA_N + KA_PAD];  // [k][n]

    const int m0 = blockIdx.y * KA_M;
    const int n0 = blockIdx.x * KA_N;
    const int tid = threadIdx.x;
    const int tx = tid & 15;        // n
    const int ty = tid >> 4;        // m

    u64 acc2[4][2];
#pragma unroll
    for (int i = 0; i < 4; i++) { acc2[i][0] = 0ull; acc2[i][1] = 0ull; }

    for (int kt = 0; kt < II; kt += KA_K) {
#pragma unroll
        for (int i = tid; i < KA_M * KA_K; i += 256) {
            int m = i >> 5, k = i & 31;
            sA[k][m] = X[(size_t)(m0 + m) * II + kt + k];
        }
#pragma unroll
        for (int i = tid; i < KA_N * KA_K; i += 256) {
            int n = i >> 5, k = i & 31;
            sB[k][n] = Wih[(size_t)(n0 + n) * II + kt + k];
        }
        __syncthreads();

#pragma unroll
        for (int k = 0; k < KA_K; k++) {
            float4 a = *(const float4*)&sA[k][ty * 4];
            ulonglong2 b2 = *(const ulonglong2*)&sB[k][tx * 4];
            u64 a0 = pk2(a.x, a.x);
            u64 a1 = pk2(a.y, a.y);
            u64 a2 = pk2(a.z, a.z);
            u64 a3 = pk2(a.w, a.w);
            acc2[0][0] = fma2(a0, b2.x, acc2[0][0]);
            acc2[0][1] = fma2(a0, b2.y, acc2[0][1]);
            acc2[1][0] = fma2(a1, b2.x, acc2[1][0]);
            acc2[1][1] = fma2(a1, b2.y, acc2[1][1]);
            acc2[2][0] = fma2(a2, b2.x, acc2[2][0]);
            acc2[2][1] = fma2(a2, b2.y, acc2[2][1]);
            acc2[3][0] = fma2(a3, b2.x, acc2[3][0]);
            acc2[3][1] = fma2(a3, b2.y, acc2[3][1]);
        }
        __syncthreads();
    }

    float bi[4];
#pragma unroll
    for (int jn = 0; jn < 4; jn++) bi[jn] = bih[n0 + tx * 4 + jn];

#pragma unroll
    for (int im = 0; im < 4; im++) {
        int m = m0 + ty * 4 + im;
        int b = m >> 9;       // /T
        int t = m & 511;      // %T
        float* dst = g_xg + ((size_t)t * BB + b) * G3 + n0 + tx * 4;
#pragma unroll
        for (int jp = 0; jp < 2; jp++) {
            float2 v = unpk2(acc2[im][jp]);
            dst[2 * jp]     = v.x + bi[2 * jp];
            dst[2 * jp + 1] = v.y + bi[2 * jp + 1];
        }
    }
}

// ---------------------------------------------------------------------------
// Kernel B: persistent GRU recurrence — REGISTER-RESIDENT WEIGHTS.
// Grid = 128 CTAs (4 batch-groups x 32 j-tiles), 256 threads, 1 CTA/SM.
// Warp w owns hidden units {j0+2w, j0+2w+1} (6 gate rows).
// Lane l owns k-granules {4l, 128+4l, 256+4l, 384+4l} (16 k-values);
// its 6x16 weight slice lives in registers for the whole kernel.
// Per step, per batch: 4 LDS.128 of h + 48 fma2 + 5-round butterfly reduce.
// Only h tile lives in smem (66 KB). No weight smem traffic at all.
// ---------------------------------------------------------------------------
#define NBT 4
#define NJT 32
#define NCTA (NBT * NJT)     // 128
#define BT 32                // batches per CTA
#define JT 16                // hidden units per CTA
#define HS 516               // smem h row stride (floats)
#define SMEM_BYTES (BT * HS * 4)

__device__ __forceinline__ void group_sync(int bt)
{
    __threadfence();          // release: h-stores visible at L2
    __syncthreads();
    if (threadIdx.x == 0) {
        volatile unsigned* vgen = &g_bar[bt].gen;
        unsigned gen = *vgen;
        if (atomicAdd(&g_bar[bt].cnt, 1u) == NJT - 1) {
            atomicExch(&g_bar[bt].cnt, 0u);
            __threadfence();
            atomicExch((unsigned*)&g_bar[bt].gen, gen + 1u);
        } else {
            while (*vgen == gen) { __nanosleep(32); }
            __threadfence();  // acquire
        }
    }
    __syncthreads();
}

__device__ __forceinline__ float sigf(float x)
{
    return 1.0f / (1.0f + expf(-x));
}

__global__ void __launch_bounds__(256, 1) gru_rec_kernel(
    const float* __restrict__ Whh,
    const float* __restrict__ bhh,
    float* __restrict__ out)
{
    extern __shared__ float smem[];
    float* sH = smem;                 // [32][HS]

    const int tid  = threadIdx.x;
    const int bt   = blockIdx.x / NJT;
    const int jt   = blockIdx.x % NJT;
    const int b0   = bt * BT;
    const int j0   = jt * JT;
    const int lane = tid & 31;
    const int w    = tid >> 5;        // warp 0..7
    const int jA   = j0 + 2 * w;      // this warp's even hidden unit

    // ---- Load this lane's weight slice into registers (constant all steps).
    // Row order: [R(jA), R(jA+1), Z(jA), Z(jA+1), N(jA), N(jA+1)].
    // wreg[r][2q+p] packs W[row_r][128q + 4*lane + 2p .. +1].
    u64 wreg[6][8];
#pragma unroll
    for (int r = 0; r < 6; r++) {
        int grow = (r >> 1) * HH + jA + (r & 1);
        const float* wrow = Whh + (size_t)grow * HH;
#pragma unroll
        for (int q = 0; q < 4; q++) {
            ulonglong2 v = *(const ulonglong2*)(wrow + q * 128 + 4 * lane);
            wreg[r][2 * q]     = v.x;
            wreg[r][2 * q + 1] = v.y;
        }
    }

    // Zero h[0] for this CTA's (b, j) tile: thread (w, lane) owns (b0+lane, jA..jA+1)
    {
        float2 z2 = make_float2(0.f, 0.f);
        *(float2*)&g_h[0][(size_t)(b0 + lane) * HH + jA] = z2;
        __threadfence();
    }

    const float bhR0 = bhh[jA],          bhR1 = bhh[jA + 1];
    const float bhZ0 = bhh[HH + jA],     bhZ1 = bhh[HH + jA + 1];
    const float bhN0 = bhh[2 * HH + jA], bhN1 = bhh[2 * HH + jA + 1];

    group_sync(bt);   // zeroed h visible within batch-group

    for (int t = 0; t < TT; t++) {
        const int cur = t & 1;

        // Prefetch this thread's x-gate values (overlaps with staging)
        const float* xb = g_xg + ((size_t)t * BB + b0 + lane) * G3 + jA;
        float2 xr = *(const float2*)(xb);
        float2 xz = *(const float2*)(xb + HH);
        float2 xn = *(const float2*)(xb + 2 * HH);

        // Stage h tile [32][512] from L2 into smem (coherent via ldcg)
        const float4* src4 = (const float4*)(g_h[cur] + (size_t)b0 * HH);
#pragma unroll
        for (int i = tid; i < BT * (HH / 4); i += 256) {
            int bl = i >> 7, k4 = i & 127;
            float4 v = __ldcg(src4 + (size_t)bl * (HH / 4) + k4);
            *(float4*)(sH + bl * HS + 4 * k4) = v;
        }
        __syncthreads();

        // Per-batch dot products; butterfly-reduced; lane b keeps batch b.
        u64 sR = 0ull, sZ = 0ull, sN = 0ull;

        for (int b = 0; b < BT; b++) {
            const float* hb = sH + b * HS + 4 * lane;
            ulonglong2 h01 = *(const ulonglong2*)(hb);         // k = 4l..4l+3
            ulonglong2 h23 = *(const ulonglong2*)(hb + 128);   // k = 128+4l..
            ulonglong2 h45 = *(const ulonglong2*)(hb + 256);
            ulonglong2 h67 = *(const ulonglong2*)(hb + 384);

            u64 aR0 = 0ull, aR1 = 0ull, aZ0 = 0ull, aZ1 = 0ull, aN0 = 0ull, aN1 = 0ull;

            aR0 = fma2(h01.x, wreg[0][0], aR0); aR0 = fma2(h01.y, wreg[0][1], aR0);
            aR1 = fma2(h01.x, wreg[1][0], aR1); aR1 = fma2(h01.y, wreg[1][1], aR1);
            aZ0 = fma2(h01.x, wreg[2][0], aZ0); aZ0 = fma2(h01.y, wreg[2][1], aZ0);
            aZ1 = fma2(h01.x, wreg[3][0], aZ1); aZ1 = fma2(h01.y, wreg[3][1], aZ1);
            aN0 = fma2(h01.x, wreg[4][0], aN0); aN0 = fma2(h01.y, wreg[4][1], aN0);
            aN1 = fma2(h01.x, wreg[5][0], aN1); aN1 = fma2(h01.y, wreg[5][1], aN1);

            aR0 = fma2(h23.x, wreg[0][2], aR0); aR0 = fma2(h23.y, wreg[0][3], aR0);
            aR1 = fma2(h23.x, wreg[1][2], aR1); aR1 = fma2(h23.y, wreg[1][3], aR1);
            aZ0 = fma2(h23.x, wreg[2][2], aZ0); aZ0 = fma2(h23.y, wreg[2][3], aZ0);
            aZ1 = fma2(h23.x, wreg[3][2], aZ1); aZ1 = fma2(h23.y, wreg[3][3], aZ1);
            aN0 = fma2(h23.x, wreg[4][2], aN0); aN0 = fma2(h23.y, wreg[4][3], aN0);
            aN1 = fma2(h23.x, wreg[5][2], aN1); aN1 = fma2(h23.y, wreg[5][3], aN1);

            aR0 = fma2(h45.x, wreg[0][4], aR0); aR0 = fma2(h45.y, wreg[0][5], aR0);
            aR1 = fma2(h45.x, wreg[1][4], aR1); aR1 = fma2(h45.y, wreg[1][5], aR1);
            aZ0 = fma2(h45.x, wreg[2][4], aZ0); aZ0 = fma2(h45.y, wreg[2][5], aZ0);
            aZ1 = fma2(h45.x, wreg[3][4], aZ1); aZ1 = fma2(h45.y, wreg[3][5], aZ1);
            aN0 = fma2(h45.x, wreg[4][4], aN0); aN0 = fma2(h45.y, wreg[4][5], aN0);
            aN1 = fma2(h45.x, wreg[5][4], aN1); aN1 = fma2(h45.y, wreg[5][5], aN1);

            aR0 = fma2(h67.x, wreg[0][6], aR0); aR0 = fma2(h67.y, wreg[0][7], aR0);
            aR1 = fma2(h67.x, wreg[1][6], aR1); aR1 = fma2(h67.y, wreg[1][7], aR1);
            aZ0 = fma2(h67.x, wreg[2][6], aZ0); aZ0 = fma2(h67.y, wreg[2][7], aZ0);
            aZ1 = fma2(h67.x, wreg[3][6], aZ1); aZ1 = fma2(h67.y, wreg[3][7], aZ1);
            aN0 = fma2(h67.x, wreg[4][6], aN0); aN0 = fma2(h67.y, wreg[4][7], aN0);
            aN1 = fma2(h67.x, wreg[5][6], aN1); aN1 = fma2(h67.y, wreg[5][7], aN1);

            // horizontal within lane, pack (j0, j1) pairs
            u64 pR = pk2(rsum2(aR0), rsum2(aR1));
            u64 pZ = pk2(rsum2(aZ0), rsum2(aZ1));
            u64 pN = pk2(rsum2(aN0), rsum2(aN1));

            // butterfly across 32 lanes (all lanes end with the total)
#pragma unroll
            for (int s = 16; s >= 1; s >>= 1) {
                pR = add2(pR, shfl_xor_u64(pR, s));
                pZ = add2(pZ, shfl_xor_u64(pZ, s));
                pN = add2(pN, shfl_xor_u64(pN, s));
            }

            if (lane == b) { sR = pR; sZ = pZ; sN = pN; }
        }

        // Gate phase: thread (w, lane) = (j-pair jA, batch b0+lane)
        float2 aR = unpk2(sR);
        float2 aZ = unpk2(sZ);
        float2 aN = unpk2(sN);
        float2 hold2 = *(const float2*)(sH + lane * HS + jA);

        // PyTorch gate order: r, z, n
        float r0v = sigf(xr.x + aR.x + bhR0);
        float z0v = sigf(xz.x + aZ.x + bhZ0);
        float n0v = tanhf(xn.x + r0v * (aN.x + bhN0));
        float hn0 = fmaf(z0v, hold2.x - n0v, n0v);   // (1-z)n + z h

        float r1v = sigf(xr.y + aR.y + bhR1);
        float z1v = sigf(xz.y + aZ.y + bhZ1);
        float n1v = tanhf(xn.y + r1v * (aN.y + bhN1));
        float hn1 = fmaf(z1v, hold2.y - n1v, n1v);

        float2 hw = make_float2(hn0, hn1);
        if (t == TT - 1) {
            *(float2*)&out[(size_t)(b0 + lane) * HH + jA] = hw;
        } else {
            __stcg((float2*)&g_h[cur ^ 1][(size_t)(b0 + lane) * HH + jA], hw);
        }

        group_sync(bt);
    }
}

// ---------------------------------------------------------------------------
// Launcher
// ---------------------------------------------------------------------------
extern "C" void kernel_launch(void* const* d_in, const int* in_sizes, int n_in,
                              void* d_out, int out_size)
{
    const float* X   = (const float*)d_in[0];  // [128,512,256]
    const float* Wih = (const float*)d_in[1];  // [1536,256]
    const float* Whh = (const float*)d_in[2];  // [1536,512]
    const float* bih = (const float*)d_in[3];  // [1536]
    const float* bhh = (const float*)d_in[4];  // [1536]
    float* out = (float*)d_out;                // [1,128,512]

    (void)in_sizes; (void)n_in; (void)out_size;

    dim3 gA(G3 / KA_N, (BB * TT) / KA_M);      // (24, 1024)
    xproj_kernel<<<gA, 256>>>(X, Wih, bih);

    cudaFuncSetAttribute(gru_rec_kernel,
                         cudaFuncAttributeMaxDynamicSharedMemorySize, SMEM_BYTES);
    gru_rec_kernel<<<NCTA, 256, SMEM_BYTES>>>(Whh, bhh, out);
}